// round 13
// baseline (speedup 1.0000x reference)
#include <cuda_runtime.h>
#include <math.h>
#include <stdint.h>

#define BT     64               // frames per block
#define NTHR   256              // 8 warps, one role each; 2 frames per lane
#define FPF    153
#define NF     114
#define HW     9

#define SM_FR   (BT * FPF)          // 9792 floats (39168 B, contiguous tile)
#define SM_HALO ((BT + 4) * HW)     // 612 floats
#define SM_OUT  (BT * NF)           // 7296 floats (29184 B, contiguous tile)
#define SMEM_BYTES ((SM_FR + SM_HALO + SM_OUT) * 4)   // 70800 bytes

__device__ __forceinline__ float fsq(float x){
    return x * rsqrtf(fmaxf(x, 1e-38f));
}
__device__ __forceinline__ float3 f3sub(float3 a, float3 b){ return make_float3(a.x-b.x, a.y-b.y, a.z-b.z); }
__device__ __forceinline__ float  f3dot(float3 a, float3 b){ return a.x*b.x + a.y*b.y + a.z*b.z; }
__device__ __forceinline__ float3 f3cross(float3 a, float3 b){
    return make_float3(a.y*b.z - a.z*b.y, a.z*b.x - a.x*b.z, a.x*b.y - a.y*b.x);
}
__device__ __forceinline__ float  f3n(float3 a){ return fsq(f3dot(a,a)); }
__device__ __forceinline__ float  fdist(float3 a, float3 b){
    float3 d = f3sub(a,b);
    float q = f3dot(d,d) + 1e-6f;
    return q * rsqrtf(q);
}
// acos via A&S 4.4.45 4-term poly
__device__ __forceinline__ float ac(float c){
    c = fminf(fmaxf(c, -1.0f + 1e-6f), 1.0f - 1e-6f);
    float xa = fabsf(c);
    float p =            -0.0187292994f;
    p = fmaf(p, xa,  0.0742610031f);
    p = fmaf(p, xa, -0.2121143956f);
    p = fmaf(p, xa,  1.5707287788f);
    float s = 1.0f - xa;
    s = s * rsqrtf(s);
    float r = p * s;
    return (c < 0.0f) ? (3.14159265358979f - r) : r;
}
__device__ __forceinline__ void finger_angles(float* o, int ko,
                                              float3 w, float3 A, float3 B, float3 C, float3 D){
    float3 e0 = f3sub(w, A), e1 = f3sub(B, A), e2 = f3sub(C, B), e3 = f3sub(D, C);
    float q0 = f3dot(e0,e0), q1 = f3dot(e1,e1), q2 = f3dot(e2,e2), q3 = f3dot(e3,e3);
    o[ko+0] = ac( f3dot(e0,e1) * rsqrtf(q0*q1 + 1e-12f));
    o[ko+1] = ac(-f3dot(e1,e2) * rsqrtf(q1*q2 + 1e-12f));
    o[ko+2] = ac(-f3dot(e2,e3) * rsqrtf(q2*q3 + 1e-12f));
}
__device__ __forceinline__ void cidx(int t, int T, int& lo, int& hi){
    if (t == 0)        { lo = 0;     hi = 2;     }
    else if (t == T-1) { lo = T - 3; hi = T - 1; }
    else               { lo = t - 1; hi = t + 1; }
}
__device__ __forceinline__ void mbar_wait_parity(uint32_t addr, uint32_t parity){
    asm volatile(
        "{\n\t"
        ".reg .pred P;\n\t"
        "WAIT_%=: \n\t"
        "mbarrier.try_wait.parity.acquire.cta.shared::cta.b64 P, [%0], %1;\n\t"
        "@P bra DONE_%=;\n\t"
        "bra WAIT_%=;\n\t"
        "DONE_%=: \n\t"
        "}"
        :: "r"(addr), "r"(parity) : "memory");
}

extern __shared__ float smem_dyn[];

__global__ void __launch_bounds__(NTHR, 3)
geo_kernel(const float* __restrict__ xyz,
           const float* __restrict__ fmask,
           const float* __restrict__ bmask,
           float* __restrict__ out, int T)
{
    __shared__ __align__(8) unsigned long long mbar;

    float* sm   = smem_dyn;                 // [BT*FPF]
    float* halo = sm + SM_FR;               // [(BT+4)*HW]
    float* so   = halo + SM_HALO;           // [BT*NF]

    const int tid = threadIdx.x;
    const long long g0 = (long long)blockIdx.x * BT;
    const int b  = (int)(g0 / T);
    const int t0 = (int)(g0 % T);

    const uint32_t mbar_a = (uint32_t)__cvta_generic_to_shared(&mbar);
    const uint32_t sm_a   = (uint32_t)__cvta_generic_to_shared(sm);
    const uint32_t so_a   = (uint32_t)__cvta_generic_to_shared(so);

    if (tid == 0){
        asm volatile("mbarrier.init.shared.b64 [%0], %1;" :: "r"(mbar_a), "r"(1) : "memory");
    }
    __syncthreads();   // mbar init visible before anyone waits

    // ---- bulk async load of the contiguous 64-frame tile (39168 B) ----
    if (tid == 0){
        const float* src = xyz + ((long long)b * T + t0) * FPF;
        asm volatile("mbarrier.arrive.expect_tx.shared.b64 _, [%0], %1;"
                     :: "r"(mbar_a), "r"((uint32_t)(SM_FR * 4)) : "memory");
        asm volatile("cp.async.bulk.shared::cta.global.mbarrier::complete_tx::bytes [%0], [%1], %2, [%3];"
                     :: "r"(sm_a), "l"(src), "r"((uint32_t)(SM_FR * 4)), "r"(mbar_a) : "memory");
    }

    // ---- manual halo load: joints 0,21,42 for frames t0-2..t0+BT+1 ----
    {
        const float* fb = xyz + (long long)b * T * FPF;
        for (int i = tid; i < SM_HALO; i += NTHR){
            int f = i / HW, jc = i % HW;
            int s = t0 - 2 + f;
            float v = 0.0f;
            if (s >= 0 && s < T){
                int j = (jc < 3) ? 0 : ((jc < 6) ? 21 : 42);
                v = fb[(long long)s * FPF + j * 3 + (jc % 3)];
            }
            halo[i] = v;
        }
    }
    __syncthreads();                 // halo visible to all warps
    mbar_wait_parity(mbar_a, 0);     // bulk tile landed

    const int role = tid >> 5;      // 0..7, one warp per role
    const int lane = tid & 31;
    const int hb = t0 - 2;

    #define PJ(j) make_float3(sm[smb + (j)*3], sm[smb + (j)*3 + 1], sm[smb + (j)*3 + 2])
    #define HLD(f, w) make_float3(halo[(f)*HW + (w)*3], halo[(f)*HW + (w)*3 + 1], halo[(f)*HW + (w)*3 + 2])

    #pragma unroll
    for (int u = 0; u < 2; ++u){
        const int fr  = lane + u * 32;
        const int t   = t0 + fr;
        const int smb = fr * FPF;
        float* o = so + fr * NF;

        if (role < 4){
            const int h  = role >> 1;
            const int bs = h * 21;
            const int ko = 34 + h * 15;
            float3 w = PJ(bs);
            if ((role & 1) == 0){
                finger_angles(o, ko + 0, w, PJ(bs+1),  PJ(bs+2),  PJ(bs+3),  PJ(bs+4));
                finger_angles(o, ko + 3, w, PJ(bs+5),  PJ(bs+6),  PJ(bs+7),  PJ(bs+8));
                finger_angles(o, ko + 6, w, PJ(bs+9),  PJ(bs+10), PJ(bs+11), PJ(bs+12));
            } else {
                finger_angles(o, ko + 9,  w, PJ(bs+13), PJ(bs+14), PJ(bs+15), PJ(bs+16));
                finger_angles(o, ko + 12, w, PJ(bs+17), PJ(bs+18), PJ(bs+19), PJ(bs+20));
                float3 v0 = f3sub(PJ(bs+5),  w), v1 = f3sub(PJ(bs+9),  w);
                float3 v2 = f3sub(PJ(bs+13), w), v3 = f3sub(PJ(bs+17), w);
                float q0 = f3dot(v0,v0), q1 = f3dot(v1,v1), q2 = f3dot(v2,v2), q3 = f3dot(v3,v3);
                o[70 + h*3 + 0] = ac(f3dot(v0,v1) * rsqrtf(q0*q1 + 1e-12f));
                o[70 + h*3 + 1] = ac(f3dot(v1,v2) * rsqrtf(q1*q2 + 1e-12f));
                o[70 + h*3 + 2] = ac(f3dot(v2,v3) * rsqrtf(q2*q3 + 1e-12f));
            }
        }
        else if (role < 6){
            const int h  = role - 4;
            const int bs = h * 21;
            float* oo = o + h * 12;
            float3 tT = PJ(bs+4),  iT = PJ(bs+8),  mT = PJ(bs+12), rT = PJ(bs+16), pT = PJ(bs+20);
            oo[0] = fdist(tT,iT); oo[1] = fdist(iT,mT); oo[2] = fdist(mT,rT);
            oo[3] = fdist(rT,pT); oo[4] = fdist(tT,pT);
            float3 tM = PJ(bs+2),  iM = PJ(bs+5),  mM = PJ(bs+9),  rM = PJ(bs+13), pM = PJ(bs+17);
            float3 tI = PJ(bs+3),  iP = PJ(bs+6),  mP = PJ(bs+10), rP = PJ(bs+14), pP = PJ(bs+18);
            oo[5] = __fdividef(fdist(tM,tT), fdist(tM,tI) + 1e-4f);
            oo[6] = __fdividef(fdist(iM,iT), fdist(iM,iP) + 1e-4f);
            oo[7] = __fdividef(fdist(mM,mT), fdist(mM,mP) + 1e-4f);
            oo[8] = __fdividef(fdist(rM,rT), fdist(rM,rP) + 1e-4f);
            oo[9] = __fdividef(fdist(pM,pT), fdist(pM,pP) + 1e-4f);
            oo[10] = iT.x - mT.x;
            oo[11] = fdist(tT, iM);
            float3 w = PJ(bs);
            float3 n = f3cross(f3sub(iM, w), f3sub(pM, w));
            float inv = rsqrtf(f3dot(n,n) + 1e-12f);
            n.x *= inv; n.y *= inv; n.z *= inv;
            o[64 + h*3 + 0] = n.x; o[64 + h*3 + 1] = n.y; o[64 + h*3 + 2] = n.z;
            o[76 + h*2] = n.y; o[77 + h*2] = n.z;
        }
        else if (role == 6){
            const float fg = fmask[(long long)b * T + t];
            float3 w0 = PJ(0), w1 = PJ(21), nose = PJ(42), chin = PJ(43), fh = PJ(44);
            float3 iT0 = PJ(8), iT1 = PJ(29);
            o[24] = fdist(w0,nose)*fg;  o[25] = fdist(w0,chin)*fg;  o[26] = fdist(w0,fh)*fg;
            o[27] = fdist(w1,nose)*fg;  o[28] = fdist(w1,chin)*fg;  o[29] = fdist(w1,fh)*fg;
            o[30] = fdist(iT0,nose)*fg; o[31] = fdist(iT0,fh)*fg;
            o[32] = fdist(iT1,nose)*fg; o[33] = fdist(iT1,fh)*fg;

            o[88] = fdist(w0, w1);
            {
                float3 rl = f3sub(w1, w0);
                float inv = rsqrtf(f3dot(rl,rl) + 1e-12f);
                o[89] = rl.x * inv; o[90] = rl.y * inv;
            }
            int lo, hi; cidx(t, T, lo, hi);
            #pragma unroll
            for (int h = 0; h < 2; ++h){
                float3 ah = HLD(hi - hb, h), an = HLD(hi - hb, 2);
                float3 bh = HLD(lo - hb, h), bn = HLD(lo - hb, 2);
                o[91 + h] = 0.5f * (f3n(f3sub(ah, an)) - f3n(f3sub(bh, bn)));
            }
            #pragma unroll
            for (int h = 0; h < 2; ++h){
                float3 a = HLD(hi - hb, h), bb = HLD(lo - hb, h);
                float3 vel = make_float3(0.5f*(a.x-bb.x), 0.5f*(a.y-bb.y), 0.5f*(a.z-bb.z));
                float qv = f3dot(vel, vel);
                float inv = rsqrtf(fmaxf(qv, 1e-12f));
                o[80 + h*3 + 0] = vel.x * inv;
                o[80 + h*3 + 1] = vel.y * inv;
                o[80 + h*3 + 2] = vel.z * inv;

                float val = 0.0f;
                if (t < T - 1){
                    int lo2, hi2; cidx(t + 1, T, lo2, hi2);
                    float3 a2 = HLD(hi2 - hb, h), b2 = HLD(lo2 - hb, h);
                    float3 v2 = make_float3(0.5f*(a2.x-b2.x), 0.5f*(a2.y-b2.y), 0.5f*(a2.z-b2.z));
                    float q2 = f3dot(v2, v2);
                    val = ac(f3dot(vel, v2) * rsqrtf(qv*q2 + 1e-12f));
                }
                o[86 + h] = val;
            }
        }
        else {
            const float bg = bmask[(long long)b * T + t];
            float3 w0 = PJ(0), w1 = PJ(21);
            int lo, hi; cidx(t, T, lo, hi);
            {
                float3 iT0 = PJ(8), iT1 = PJ(29);
                float3 mT0 = PJ(12), rT0 = PJ(16), mT1 = PJ(33), rT1 = PJ(37);
                o[93] = iT0.x - mT0.x; o[94] = mT0.x - rT0.x;
                o[95] = iT1.x - mT1.x; o[96] = mT1.x - rT1.x;
            }
            float3 vel[2];
            #pragma unroll
            for (int h = 0; h < 2; ++h){
                float3 a = HLD(hi - hb, h), bb = HLD(lo - hb, h);
                vel[h] = make_float3(0.5f*(a.x-bb.x), 0.5f*(a.y-bb.y), 0.5f*(a.z-bb.z));
            }
            {
                float q0 = f3dot(vel[0],vel[0]), q1 = f3dot(vel[1],vel[1]);
                o[97] = f3dot(vel[0], vel[1]) * rsqrtf(q0*q1 + 1e-12f);
                o[98] = fsq(q0); o[99] = fsq(q1);
            }
            #pragma unroll
            for (int h = 0; h < 2; ++h){
                int l1, h1; cidx(hi, T, l1, h1);
                int l2, h2; cidx(lo, T, l2, h2);
                float3 A = HLD(h1 - hb, h), B = HLD(l1 - hb, h);
                float3 C = HLD(h2 - hb, h), D = HLD(l2 - hb, h);
                float3 chi = make_float3(0.5f*(A.x-B.x), 0.5f*(A.y-B.y), 0.5f*(A.z-B.z));
                float3 clo = make_float3(0.5f*(C.x-D.x), 0.5f*(C.y-D.y), 0.5f*(C.z-D.z));
                float3 acc = make_float3(0.5f*(chi.x-clo.x), 0.5f*(chi.y-clo.y), 0.5f*(chi.z-clo.z));
                o[100 + h] = f3n(acc);
            }
            {
                float hd = f3n(f3sub(w0, w1));
                o[102] = __fdividef(1.0f, 1.0f + __expf(-5.0f * (0.05f - hd)));
            }
            {
                float3 lsh = PJ(45), rsh = PJ(46), lel = PJ(47), rel2 = PJ(48), ul = PJ(49), ll = PJ(50);
                float shmx = 0.5f * (lsh.x + rsh.x);
                float shmy = 0.5f * (lsh.y + rsh.y);
                float shw = fdist(lsh, rsh);
                float invw = __fdividef(1.0f, shw + 1e-6f);
                o[103] = (w0.y - shmy) * invw * bg;
                o[104] = (w0.x - shmx) * invw * bg;
                o[105] = fdist(w0, lsh) * bg;
                o[106] = fdist(w0, lel) * bg;
                o[107] = (w1.y - shmy) * invw * bg;
                o[108] = (w1.x - shmx) * invw * bg;
                o[109] = fdist(w1, rsh) * bg;
                o[110] = fdist(w1, rel2) * bg;
                o[111] = shw * bg;
                float3 mo = make_float3(0.5f*(ul.x+ll.x), 0.5f*(ul.y+ll.y), 0.5f*(ul.z+ll.z));
                o[112] = fdist(w0, mo) * bg;
                o[113] = fdist(w1, mo) * bg;
            }
        }
    }
    #undef PJ
    #undef HLD

    // ---- bulk async flush of the contiguous 29184-B output tile ----
    __syncthreads();                 // all feature STS done
    if (tid == 0){
        asm volatile("fence.proxy.async.shared::cta;" ::: "memory");
        float* dstg = out + ((long long)b * T + t0) * NF;
        asm volatile("cp.async.bulk.global.shared::cta.bulk_group [%0], [%1], %2;"
                     :: "l"(dstg), "r"(so_a), "r"((uint32_t)(SM_OUT * 4)) : "memory");
        asm volatile("cp.async.bulk.commit_group;" ::: "memory");
        asm volatile("cp.async.bulk.wait_group 0;" ::: "memory");
    }
}

extern "C" void kernel_launch(void* const* d_in, const int* in_sizes, int n_in,
                              void* d_out, int out_size)
{
    const float* xyz = (const float*)d_in[0];
    const float* fm  = (const float*)d_in[1];
    const float* bm  = (const float*)d_in[2];
    float* out = (float*)d_out;

    const int T = 512;
    const int BTtot = in_sizes[1];     // B*T
    const int blocks = BTtot / BT;     // 2048

    cudaFuncSetAttribute(geo_kernel, cudaFuncAttributeMaxDynamicSharedMemorySize, SMEM_BYTES);
    geo_kernel<<<blocks, NTHR, SMEM_BYTES>>>(xyz, fm, bm, out, T);
}

// round 16
// speedup vs baseline: 1.5629x; 1.5629x over previous
#include <cuda_runtime.h>
#include <math.h>
#include <stdint.h>

#define BT     32               // frames per block
#define NTHR   256              // 8 warps, one role each
#define FPF    153
#define NF     114
#define HW     9

#define SM_FR   (BT * FPF)          // 4896 floats (19584 B, contiguous tile)
#define SM_HALO ((BT + 4) * HW)     // 324 floats
#define SM_OUT  (BT * NF)           // 3648 floats (14592 B, contiguous tile)
#define SMEM_BYTES ((SM_FR + SM_HALO + SM_OUT) * 4)   // 35472 bytes

__device__ __forceinline__ float fsq(float x){
    return x * rsqrtf(fmaxf(x, 1e-38f));
}
__device__ __forceinline__ float3 f3sub(float3 a, float3 b){ return make_float3(a.x-b.x, a.y-b.y, a.z-b.z); }
__device__ __forceinline__ float  f3dot(float3 a, float3 b){ return a.x*b.x + a.y*b.y + a.z*b.z; }
__device__ __forceinline__ float3 f3cross(float3 a, float3 b){
    return make_float3(a.y*b.z - a.z*b.y, a.z*b.x - a.x*b.z, a.x*b.y - a.y*b.x);
}
__device__ __forceinline__ float  f3n(float3 a){ return fsq(f3dot(a,a)); }
__device__ __forceinline__ float  fdist(float3 a, float3 b){
    float3 d = f3sub(a,b);
    float q = f3dot(d,d) + 1e-6f;
    return q * rsqrtf(q);
}
// acos via A&S 4.4.45 4-term poly
__device__ __forceinline__ float ac(float c){
    c = fminf(fmaxf(c, -1.0f + 1e-6f), 1.0f - 1e-6f);
    float xa = fabsf(c);
    float p =            -0.0187292994f;
    p = fmaf(p, xa,  0.0742610031f);
    p = fmaf(p, xa, -0.2121143956f);
    p = fmaf(p, xa,  1.5707287788f);
    float s = 1.0f - xa;
    s = s * rsqrtf(s);
    float r = p * s;
    return (c < 0.0f) ? (3.14159265358979f - r) : r;
}
__device__ __forceinline__ void finger_angles(float* o, int ko,
                                              float3 w, float3 A, float3 B, float3 C, float3 D){
    float3 e0 = f3sub(w, A), e1 = f3sub(B, A), e2 = f3sub(C, B), e3 = f3sub(D, C);
    float q0 = f3dot(e0,e0), q1 = f3dot(e1,e1), q2 = f3dot(e2,e2), q3 = f3dot(e3,e3);
    o[ko+0] = ac( f3dot(e0,e1) * rsqrtf(q0*q1 + 1e-12f));
    o[ko+1] = ac(-f3dot(e1,e2) * rsqrtf(q1*q2 + 1e-12f));
    o[ko+2] = ac(-f3dot(e2,e3) * rsqrtf(q2*q3 + 1e-12f));
}
__device__ __forceinline__ void cidx(int t, int T, int& lo, int& hi){
    if (t == 0)        { lo = 0;     hi = 2;     }
    else if (t == T-1) { lo = T - 3; hi = T - 1; }
    else               { lo = t - 1; hi = t + 1; }
}
__device__ __forceinline__ void mbar_wait_parity(uint32_t addr, uint32_t parity){
    asm volatile(
        "{\n\t"
        ".reg .pred P;\n\t"
        "WAIT_%=: \n\t"
        "mbarrier.try_wait.parity.acquire.cta.shared::cta.b64 P, [%0], %1;\n\t"
        "@P bra DONE_%=;\n\t"
        "bra WAIT_%=;\n\t"
        "DONE_%=: \n\t"
        "}"
        :: "r"(addr), "r"(parity) : "memory");
}

extern __shared__ float smem_dyn[];

__global__ void __launch_bounds__(NTHR, 6)
geo_kernel(const float* __restrict__ xyz,
           const float* __restrict__ fmask,
           const float* __restrict__ bmask,
           float* __restrict__ out, int T)
{
    __shared__ __align__(8) unsigned long long mbar;

    float* sm   = smem_dyn;                 // [BT*FPF]
    float* halo = sm + SM_FR;               // [(BT+4)*HW]
    float* so   = halo + SM_HALO;           // [BT*NF]

    const int tid = threadIdx.x;
    const long long g0 = (long long)blockIdx.x * BT;
    const int b  = (int)(g0 / T);
    const int t0 = (int)(g0 % T);

    const uint32_t mbar_a = (uint32_t)__cvta_generic_to_shared(&mbar);
    const uint32_t sm_a   = (uint32_t)__cvta_generic_to_shared(sm);
    const uint32_t so_a   = (uint32_t)__cvta_generic_to_shared(so);

    // tid0: init mbar, then immediately start the bulk load. Other threads
    // only touch mbar after the halo __syncthreads below (which orders init).
    if (tid == 0){
        asm volatile("mbarrier.init.shared.b64 [%0], %1;" :: "r"(mbar_a), "r"(1) : "memory");
        const float* src = xyz + ((long long)b * T + t0) * FPF;
        asm volatile("mbarrier.arrive.expect_tx.shared.b64 _, [%0], %1;"
                     :: "r"(mbar_a), "r"((uint32_t)(SM_FR * 4)) : "memory");
        asm volatile("cp.async.bulk.shared::cta.global.mbarrier::complete_tx::bytes [%0], [%1], %2, [%3];"
                     :: "r"(sm_a), "l"(src), "r"((uint32_t)(SM_FR * 4)), "r"(mbar_a) : "memory");
    }

    const int role = tid >> 5;      // 0..7, one warp per role
    const int fr   = tid & 31;
    const int t    = t0 + fr;
    const int hb   = t0 - 2;

    // hoist mask loads above the mbar wait (hide gmem latency under bulk copy)
    float fg = 0.0f, bg = 0.0f;
    if (role == 6) fg = fmask[(long long)b * T + t];
    if (role == 7) bg = bmask[(long long)b * T + t];

    // ---- manual halo load: joints 0,21,42 for frames t0-2..t0+BT+1 ----
    {
        const float* fb = xyz + (long long)b * T * FPF;
        for (int i = tid; i < SM_HALO; i += NTHR){
            int f = i / HW, jc = i % HW;
            int s = t0 - 2 + f;
            float v = 0.0f;
            if (s >= 0 && s < T){
                int j = (jc < 3) ? 0 : ((jc < 6) ? 21 : 42);
                v = fb[(long long)s * FPF + j * 3 + (jc % 3)];
            }
            halo[i] = v;
        }
    }
    __syncthreads();                 // halo + mbar init visible to all warps
    mbar_wait_parity(mbar_a, 0);     // bulk tile landed

    const int smb = fr * FPF;
    #define PJ(j) make_float3(sm[smb + (j)*3], sm[smb + (j)*3 + 1], sm[smb + (j)*3 + 2])
    #define HLD(f, w) make_float3(halo[(f)*HW + (w)*3], halo[(f)*HW + (w)*3 + 1], halo[(f)*HW + (w)*3 + 2])

    float* o = so + fr * NF;

    if (role < 4){
        const int h  = role >> 1;
        const int bs = h * 21;
        const int ko = 34 + h * 15;
        float3 w = PJ(bs);
        if ((role & 1) == 0){
            finger_angles(o, ko + 0, w, PJ(bs+1),  PJ(bs+2),  PJ(bs+3),  PJ(bs+4));
            finger_angles(o, ko + 3, w, PJ(bs+5),  PJ(bs+6),  PJ(bs+7),  PJ(bs+8));
            finger_angles(o, ko + 6, w, PJ(bs+9),  PJ(bs+10), PJ(bs+11), PJ(bs+12));
        } else {
            finger_angles(o, ko + 9,  w, PJ(bs+13), PJ(bs+14), PJ(bs+15), PJ(bs+16));
            finger_angles(o, ko + 12, w, PJ(bs+17), PJ(bs+18), PJ(bs+19), PJ(bs+20));
            float3 v0 = f3sub(PJ(bs+5),  w), v1 = f3sub(PJ(bs+9),  w);
            float3 v2 = f3sub(PJ(bs+13), w), v3 = f3sub(PJ(bs+17), w);
            float q0 = f3dot(v0,v0), q1 = f3dot(v1,v1), q2 = f3dot(v2,v2), q3 = f3dot(v3,v3);
            o[70 + h*3 + 0] = ac(f3dot(v0,v1) * rsqrtf(q0*q1 + 1e-12f));
            o[70 + h*3 + 1] = ac(f3dot(v1,v2) * rsqrtf(q1*q2 + 1e-12f));
            o[70 + h*3 + 2] = ac(f3dot(v2,v3) * rsqrtf(q2*q3 + 1e-12f));
        }
    }
    else if (role < 6){
        const int h  = role - 4;
        const int bs = h * 21;
        float* oo = o + h * 12;
        float3 tT = PJ(bs+4),  iT = PJ(bs+8),  mT = PJ(bs+12), rT = PJ(bs+16), pT = PJ(bs+20);
        oo[0] = fdist(tT,iT); oo[1] = fdist(iT,mT); oo[2] = fdist(mT,rT);
        oo[3] = fdist(rT,pT); oo[4] = fdist(tT,pT);
        float3 tM = PJ(bs+2),  iM = PJ(bs+5),  mM = PJ(bs+9),  rM = PJ(bs+13), pM = PJ(bs+17);
        float3 tI = PJ(bs+3),  iP = PJ(bs+6),  mP = PJ(bs+10), rP = PJ(bs+14), pP = PJ(bs+18);
        oo[5] = __fdividef(fdist(tM,tT), fdist(tM,tI) + 1e-4f);
        oo[6] = __fdividef(fdist(iM,iT), fdist(iM,iP) + 1e-4f);
        oo[7] = __fdividef(fdist(mM,mT), fdist(mM,mP) + 1e-4f);
        oo[8] = __fdividef(fdist(rM,rT), fdist(rM,rP) + 1e-4f);
        oo[9] = __fdividef(fdist(pM,pT), fdist(pM,pP) + 1e-4f);
        oo[10] = iT.x - mT.x;
        oo[11] = fdist(tT, iM);
        // tip x-diffs (moved from role 7; registers already live)
        o[93 + h*2 + 0] = iT.x - mT.x;
        o[93 + h*2 + 1] = mT.x - rT.x;
        float3 w = PJ(bs);
        float3 n = f3cross(f3sub(iM, w), f3sub(pM, w));
        float inv = rsqrtf(f3dot(n,n) + 1e-12f);
        n.x *= inv; n.y *= inv; n.z *= inv;
        o[64 + h*3 + 0] = n.x; o[64 + h*3 + 1] = n.y; o[64 + h*3 + 2] = n.z;
        o[76 + h*2] = n.y; o[77 + h*2] = n.z;
    }
    else if (role == 6){
        float3 w0 = PJ(0), w1 = PJ(21), nose = PJ(42), chin = PJ(43), fh = PJ(44);
        float3 iT0 = PJ(8), iT1 = PJ(29);
        o[24] = fdist(w0,nose)*fg;  o[25] = fdist(w0,chin)*fg;  o[26] = fdist(w0,fh)*fg;
        o[27] = fdist(w1,nose)*fg;  o[28] = fdist(w1,chin)*fg;  o[29] = fdist(w1,fh)*fg;
        o[30] = fdist(iT0,nose)*fg; o[31] = fdist(iT0,fh)*fg;
        o[32] = fdist(iT1,nose)*fg; o[33] = fdist(iT1,fh)*fg;

        o[88] = fdist(w0, w1);
        {
            float3 rl = f3sub(w1, w0);
            float inv = rsqrtf(f3dot(rl,rl) + 1e-12f);
            o[89] = rl.x * inv; o[90] = rl.y * inv;
        }
        // proximity sigmoid (moved from role 7; w0/w1 live)
        {
            float hd = f3n(f3sub(w0, w1));
            o[102] = __fdividef(1.0f, 1.0f + __expf(-5.0f * (0.05f - hd)));
        }
        int lo, hi; cidx(t, T, lo, hi);
        #pragma unroll
        for (int h = 0; h < 2; ++h){
            float3 ah = HLD(hi - hb, h), an = HLD(hi - hb, 2);
            float3 bh = HLD(lo - hb, h), bn = HLD(lo - hb, 2);
            o[91 + h] = 0.5f * (f3n(f3sub(ah, an)) - f3n(f3sub(bh, bn)));
        }
        #pragma unroll
        for (int h = 0; h < 2; ++h){
            float3 a = HLD(hi - hb, h), bb = HLD(lo - hb, h);
            float3 vel = make_float3(0.5f*(a.x-bb.x), 0.5f*(a.y-bb.y), 0.5f*(a.z-bb.z));
            float qv = f3dot(vel, vel);
            float inv = rsqrtf(fmaxf(qv, 1e-12f));
            o[80 + h*3 + 0] = vel.x * inv;
            o[80 + h*3 + 1] = vel.y * inv;
            o[80 + h*3 + 2] = vel.z * inv;

            float val = 0.0f;
            if (t < T - 1){
                int lo2, hi2; cidx(t + 1, T, lo2, hi2);
                float3 a2 = HLD(hi2 - hb, h), b2 = HLD(lo2 - hb, h);
                float3 v2 = make_float3(0.5f*(a2.x-b2.x), 0.5f*(a2.y-b2.y), 0.5f*(a2.z-b2.z));
                float q2 = f3dot(v2, v2);
                val = ac(f3dot(vel, v2) * rsqrtf(qv*q2 + 1e-12f));
            }
            o[86 + h] = val;
        }
    }
    else {
        float3 w0 = PJ(0), w1 = PJ(21);
        int lo, hi; cidx(t, T, lo, hi);
        float3 vel[2];
        #pragma unroll
        for (int h = 0; h < 2; ++h){
            float3 a = HLD(hi - hb, h), bb = HLD(lo - hb, h);
            vel[h] = make_float3(0.5f*(a.x-bb.x), 0.5f*(a.y-bb.y), 0.5f*(a.z-bb.z));
        }
        {
            float q0 = f3dot(vel[0],vel[0]), q1 = f3dot(vel[1],vel[1]);
            o[97] = f3dot(vel[0], vel[1]) * rsqrtf(q0*q1 + 1e-12f);
            o[98] = fsq(q0); o[99] = fsq(q1);
        }
        #pragma unroll
        for (int h = 0; h < 2; ++h){
            int l1, h1; cidx(hi, T, l1, h1);
            int l2, h2; cidx(lo, T, l2, h2);
            float3 A = HLD(h1 - hb, h), B = HLD(l1 - hb, h);
            float3 C = HLD(h2 - hb, h), D = HLD(l2 - hb, h);
            float3 chi = make_float3(0.5f*(A.x-B.x), 0.5f*(A.y-B.y), 0.5f*(A.z-B.z));
            float3 clo = make_float3(0.5f*(C.x-D.x), 0.5f*(C.y-D.y), 0.5f*(C.z-D.z));
            float3 acc = make_float3(0.5f*(chi.x-clo.x), 0.5f*(chi.y-clo.y), 0.5f*(chi.z-clo.z));
            o[100 + h] = f3n(acc);
        }
        {
            float3 lsh = PJ(45), rsh = PJ(46), lel = PJ(47), rel2 = PJ(48), ul = PJ(49), ll = PJ(50);
            float shmx = 0.5f * (lsh.x + rsh.x);
            float shmy = 0.5f * (lsh.y + rsh.y);
            float shw = fdist(lsh, rsh);
            float invw = __fdividef(1.0f, shw + 1e-6f);
            o[103] = (w0.y - shmy) * invw * bg;
            o[104] = (w0.x - shmx) * invw * bg;
            o[105] = fdist(w0, lsh) * bg;
            o[106] = fdist(w0, lel) * bg;
            o[107] = (w1.y - shmy) * invw * bg;
            o[108] = (w1.x - shmx) * invw * bg;
            o[109] = fdist(w1, rsh) * bg;
            o[110] = fdist(w1, rel2) * bg;
            o[111] = shw * bg;
            float3 mo = make_float3(0.5f*(ul.x+ll.x), 0.5f*(ul.y+ll.y), 0.5f*(ul.z+ll.z));
            o[112] = fdist(w0, mo) * bg;
            o[113] = fdist(w1, mo) * bg;
        }
    }
    #undef PJ
    #undef HLD

    // ---- bulk async flush of the contiguous 14592-B output tile ----
    __syncthreads();                 // all feature STS done
    if (tid == 0){
        asm volatile("fence.proxy.async.shared::cta;" ::: "memory");
        float* dstg = out + ((long long)b * T + t0) * NF;
        asm volatile("cp.async.bulk.global.shared::cta.bulk_group [%0], [%1], %2;"
                     :: "l"(dstg), "r"(so_a), "r"((uint32_t)(SM_OUT * 4)) : "memory");
        asm volatile("cp.async.bulk.commit_group;" ::: "memory");
        asm volatile("cp.async.bulk.wait_group 0;" ::: "memory");
    }
}

extern "C" void kernel_launch(void* const* d_in, const int* in_sizes, int n_in,
                              void* d_out, int out_size)
{
    const float* xyz = (const float*)d_in[0];
    const float* fm  = (const float*)d_in[1];
    const float* bm  = (const float*)d_in[2];
    float* out = (float*)d_out;

    const int T = 512;
    const int BTtot = in_sizes[1];     // B*T
    const int blocks = BTtot / BT;     // 4096

    cudaFuncSetAttribute(geo_kernel, cudaFuncAttributeMaxDynamicSharedMemorySize, SMEM_BYTES);
    geo_kernel<<<blocks, NTHR, SMEM_BYTES>>>(xyz, fm, bm, out, T);
}